// round 1
// baseline (speedup 1.0000x reference)
#include <cuda_runtime.h>

// Problem constants (fixed by the dataset): B=8, S=2048, D=1024, F=64, TOPK=8
#define Dd   1024
#define Ff   64
#define FO   192          // 3*F outputs per token (top | feat | gates)
#define TM   64           // tokens per block
#define TK   32           // K chunk
#define XSP  36           // xs row pitch (floats), padded
#define WSP  196          // ws row pitch (floats), padded

// Repacked weights: W_all[k][n], n in [0,192): [W_top | W_feat | W_gates^T]
__device__ float g_Wall[Dd * FO];

typedef unsigned long long ull;

__device__ __forceinline__ ull pack2(float lo, float hi) {
    ull r;
    asm("mov.b64 %0, {%1, %2};" : "=l"(r) : "f"(lo), "f"(hi));
    return r;
}
__device__ __forceinline__ void unpack2(ull v, float &lo, float &hi) {
    asm("mov.b64 {%0, %1}, %2;" : "=f"(lo), "=f"(hi) : "l"(v));
}
// Packed dual-FMA (Blackwell FFMA2): 2 fp32 FMAs per instruction.
__device__ __forceinline__ ull ffma2(ull a, ull b, ull c) {
    ull d;
    asm("fma.rn.f32x2 %0, %1, %2, %3;" : "=l"(d) : "l"(a), "l"(b), "l"(c));
    return d;
}

__global__ void repack_kernel(const float* __restrict__ Wt,
                              const float* __restrict__ Wf,
                              const float* __restrict__ Wg) {
    int i = blockIdx.x * 256 + threadIdx.x;
    if (i >= Dd * FO) return;
    int k = i / FO;
    int n = i - k * FO;
    float v;
    if (n < Ff)            v = Wt[k * Ff + n];
    else if (n < 2 * Ff)   v = Wf[k * Ff + (n - Ff)];
    else                   v = Wg[(size_t)(n - 2 * Ff) * Dd + k];
    g_Wall[i] = v;
}

__global__ __launch_bounds__(256)
void moe_gate_kernel(const float* __restrict__ x,
                     const float* __restrict__ b_top,
                     const float* __restrict__ b_feat,
                     const float* __restrict__ b_gates,
                     const float* __restrict__ alpha,
                     const int*   __restrict__ nump,
                     float* __restrict__ out) {
    extern __shared__ float smf[];
    float* xs = smf;              // [TM][XSP]
    float* ws = smf + TM * XSP;   // [TK][WSP]

    const int tid  = threadIdx.x;
    const int tok0 = blockIdx.x * TM;
    const int ty   = tid >> 4;    // 0..15
    const int tx   = tid & 15;    // 0..15
    const int r0   = ty * 4;      // token rows 4
    const int c0   = tx * 12;     // output cols 12

    ull acc[4][6];
#pragma unroll
    for (int i = 0; i < 4; i++)
#pragma unroll
        for (int j = 0; j < 6; j++) acc[i][j] = 0ull;

    // ---- tile loaders (registers <-> gmem <-> smem) ----
    const int xrow = tid >> 3;         // 0..31
    const int xcol = (tid & 7) * 4;    // float4 col
    const float* gx = x + (size_t)(tok0 + xrow) * Dd + xcol;

    float4 xr[2];
    float4 wr[6];

    auto load_tiles = [&](int kb) {
#pragma unroll
        for (int p = 0; p < 2; p++)
            xr[p] = *(const float4*)(gx + (size_t)(p * 32) * Dd + kb);
        const float* gw = g_Wall + (size_t)kb * FO;
#pragma unroll
        for (int p = 0; p < 6; p++) {
            int idx4 = p * 256 + tid;
            int kk = idx4 / 48;
            int cc = (idx4 - kk * 48) * 4;
            wr[p] = *(const float4*)(gw + kk * FO + cc);
        }
    };
    auto store_tiles = [&]() {
#pragma unroll
        for (int p = 0; p < 2; p++)
            *(float4*)(xs + (xrow + p * 32) * XSP + xcol) = xr[p];
#pragma unroll
        for (int p = 0; p < 6; p++) {
            int idx4 = p * 256 + tid;
            int kk = idx4 / 48;
            int cc = (idx4 - kk * 48) * 4;
            *(float4*)(ws + kk * WSP + cc) = wr[p];
        }
    };

    load_tiles(0);
    store_tiles();
    __syncthreads();

    for (int kb = 0; kb < Dd; kb += TK) {
        const bool has_next = (kb + TK) < Dd;
        if (has_next) load_tiles(kb + TK);

        // ---- FFMA2 micro-kernel over the smem tile ----
#pragma unroll 2
        for (int k4 = 0; k4 < TK; k4 += 4) {
            float4 a4[4];
#pragma unroll
            for (int i = 0; i < 4; i++)
                a4[i] = *(const float4*)(xs + (r0 + i) * XSP + k4);
#pragma unroll
            for (int kk = 0; kk < 4; kk++) {
                const ull* wrow = (const ull*)(ws + (k4 + kk) * WSP + c0);
                ull b0 = wrow[0], b1 = wrow[1], b2 = wrow[2];
                ull b3 = wrow[3], b4 = wrow[4], b5 = wrow[5];
#pragma unroll
                for (int i = 0; i < 4; i++) {
                    const float* af = (const float*)&a4[i];
                    ull ax = pack2(af[kk], af[kk]);
                    acc[i][0] = ffma2(ax, b0, acc[i][0]);
                    acc[i][1] = ffma2(ax, b1, acc[i][1]);
                    acc[i][2] = ffma2(ax, b2, acc[i][2]);
                    acc[i][3] = ffma2(ax, b3, acc[i][3]);
                    acc[i][4] = ffma2(ax, b4, acc[i][4]);
                    acc[i][5] = ffma2(ax, b5, acc[i][5]);
                }
            }
        }

        if (has_next) {
            __syncthreads();
            store_tiles();
            __syncthreads();
        }
    }

    // ---- dump results to smem: res[TM][FO], stride 192 (rotation avoids conflicts) ----
    __syncthreads();
#pragma unroll
    for (int i = 0; i < 4; i++)
#pragma unroll
        for (int j = 0; j < 6; j++) {
            float lo, hi;
            unpack2(acc[i][j], lo, hi);
            smf[(r0 + i) * FO + c0 + 2 * j]     = lo;
            smf[(r0 + i) * FO + c0 + 2 * j + 1] = hi;
        }
    __syncthreads();

    // ---- per-token epilogue: one thread per token ----
    if (tid < TM) {
        float* r = smf + tid * FO;
        const int rot = tid & (Ff - 1);

        const float av = alpha[0];
        const float a  = 1.0f / (1.0f + __expf(-av));
        int num = nump ? *nump : 8;
        if (num < 1)  num = 1;
        if (num > Ff) num = Ff;

        // biases + gate sigmoid (rotated indexing -> conflict-free)
        for (int f0 = 0; f0 < Ff; ++f0) {
            int f = (f0 + rot) & (Ff - 1);
            r[f]          += b_top[f];
            r[Ff + f]     += b_feat[f];
            float g = r[2 * Ff + f] + b_gates[f];
            r[2 * Ff + f] = 1.0f / (1.0f + __expf(-g));
        }

        // dense branch: softmax(feat) dot gates
        float m2 = -3.4e38f;
        for (int f0 = 0; f0 < Ff; ++f0) {
            int f = (f0 + rot) & (Ff - 1);
            m2 = fmaxf(m2, r[Ff + f]);
        }
        float s2 = 0.0f, ds = 0.0f;
        for (int f0 = 0; f0 < Ff; ++f0) {
            int f = (f0 + rot) & (Ff - 1);
            float e = __expf(r[Ff + f] - m2);
            s2 += e;
            ds += e * r[2 * Ff + f];
        }
        float dense = ds / s2;

        // top-k branch: streaming selection + softmax over selected
        float v0 = 0.0f, se = 0.0f, ta = 0.0f;
        for (int t = 0; t < num; ++t) {
            float best = -3.4e38f;
            int bi = 0;
            for (int f0 = 0; f0 < Ff; ++f0) {
                int f = (f0 + rot) & (Ff - 1);
                float v = r[f];
                if (v > best) { best = v; bi = f; }
            }
            if (t == 0) v0 = best;
            float e = __expf(best - v0);
            se += e;
            ta += e * r[2 * Ff + bi];
            r[bi] = -3.4e38f;
        }
        float topp = ta / se;

        out[tok0 + tid] = a * topp + (1.0f - a) * dense;
    }
}

extern "C" void kernel_launch(void* const* d_in, const int* in_sizes, int n_in,
                              void* d_out, int out_size) {
    const float* x  = (const float*)d_in[0];
    const float* Wt = (const float*)d_in[1];
    const float* bt = (const float*)d_in[2];
    const float* Wf = (const float*)d_in[3];
    const float* bf = (const float*)d_in[4];
    const float* Wg = (const float*)d_in[5];
    const float* bg = (const float*)d_in[6];
    const float* al = (const float*)d_in[7];
    const int*   nm = (n_in > 8) ? (const int*)d_in[8] : nullptr;
    float* out = (float*)d_out;

    const int tokens = in_sizes[0] / Dd;   // 16384

    repack_kernel<<<(Dd * FO + 255) / 256, 256>>>(Wt, Wf, Wg);

    size_t smem = (size_t)TM * FO * sizeof(float);  // 49152 B (>= pipeline 34304 B)
    moe_gate_kernel<<<tokens / TM, 256, smem>>>(x, bt, bf, bg, al, nm, out);
}

// round 4
// speedup vs baseline: 2.2425x; 2.2425x over previous
#include <cuda_runtime.h>
#include <cuda_bf16.h>
#include <cstdint>

// Problem constants: B=8, S=2048, D=1024, F=64, TOPK=8
#define Dd     1024
#define Ff     64
#define FO     192            // 3*F fused outputs (top | feat | gates)
#define TM     128            // tokens per CTA
#define KC     32             // K chunk
#define NCH    (Dd / KC)      // 32
#define TOKENS 16384
#define APB    80             // smem row pitch bytes (conflict-free)
#define ABUF   (2 * TM * APB)     // 20480 B  (A hi + A lo)
#define BBUF   (2 * FO * APB)     // 30720 B  (B hi + B lo)
#define BUFSZ  (ABUF + BBUF)      // 51200 B
#define SMEMSZ (2 * BUFSZ)        // 102400 B (double buffered; epi overlays)
#define EPIP   194                // epilogue row pitch (floats)

// Repacked weights, bf16 hi/lo split, n-major [FO][Dd]
__device__ __nv_bfloat16 g_Whi[FO * Dd];
__device__ __nv_bfloat16 g_Wlo[FO * Dd];

__device__ __forceinline__ void mma16816(float* c, const uint32_t* a,
                                         uint32_t b0, uint32_t b1) {
    asm("mma.sync.aligned.m16n8k16.row.col.f32.bf16.bf16.f32 "
        "{%0,%1,%2,%3}, {%4,%5,%6,%7}, {%8,%9}, {%0,%1,%2,%3};"
        : "+f"(c[0]), "+f"(c[1]), "+f"(c[2]), "+f"(c[3])
        : "r"(a[0]), "r"(a[1]), "r"(a[2]), "r"(a[3]), "r"(b0), "r"(b1));
}
__device__ __forceinline__ uint32_t pkbf2(float a, float b) {
    __nv_bfloat162 t = __halves2bfloat162(__float2bfloat16_rn(a),
                                          __float2bfloat16_rn(b));
    uint32_t u; memcpy(&u, &t, 4); return u;
}

__global__ __launch_bounds__(256)
void repack_kernel(const float* __restrict__ Wt,
                   const float* __restrict__ Wf,
                   const float* __restrict__ Wg) {
    int i = blockIdx.x * 256 + threadIdx.x;
    if (i >= FO * Dd) return;
    int n = i / Dd, k = i - n * Dd;
    float w;
    if (n < Ff)          w = Wt[k * Ff + n];
    else if (n < 2 * Ff) w = Wf[k * Ff + (n - Ff)];
    else                 w = Wg[(size_t)(n - 2 * Ff) * Dd + k];
    __nv_bfloat16 hi = __float2bfloat16_rn(w);
    float lo = w - __bfloat162float(hi);
    g_Whi[n * Dd + k] = hi;
    g_Wlo[n * Dd + k] = __float2bfloat16_rn(lo);
}

__global__ __launch_bounds__(256, 1)
void moe_mma_kernel(const float* __restrict__ x,
                    const float* __restrict__ b_top,
                    const float* __restrict__ b_feat,
                    const float* __restrict__ b_gates,
                    const float* __restrict__ alpha,
                    const int*   __restrict__ nump,
                    float* __restrict__ out) {
    extern __shared__ char smc[];

    const int tid    = threadIdx.x;
    const int wid    = tid >> 5;
    const int lane   = tid & 31;
    const int warp_m = wid & 3;     // M 32-row block
    const int warp_n = wid >> 2;    // N 96-col block
    const int tok0   = blockIdx.x * TM;

    float acc[2][12][4];
#pragma unroll
    for (int i = 0; i < 2; i++)
#pragma unroll
        for (int j = 0; j < 12; j++)
#pragma unroll
            for (int q = 0; q < 4; q++) acc[i][j][q] = 0.0f;

    // ---- global->reg loaders (register double buffering) ----
    const int arow  = tid >> 1;      // token row 0..127
    const int ahalf = tid & 1;       // k half (16 floats)
    float4 aReg[4];
    uint4  bReg[6];

    auto loadA = [&](int kb) {
        const float* gx = x + (size_t)(tok0 + arow) * Dd + kb + ahalf * 16;
#pragma unroll
        for (int j = 0; j < 4; j++) aReg[j] = *(const float4*)(gx + 4 * j);
    };
    auto loadB = [&](int kb) {
#pragma unroll
        for (int p = 0; p < 6; p++) {
            int u   = p * 256 + tid;           // 0..1535
            int mat = (u >= 768);
            int v   = mat ? (u - 768) : u;     // FIXED: was u & 767
            int n   = v >> 2, q = v & 3;
            const __nv_bfloat16* src =
                (mat ? g_Wlo : g_Whi) + (size_t)n * Dd + kb + q * 8;
            bReg[p] = *(const uint4*)src;
        }
    };
    auto stsAll = [&](int buf) {
        char* A = smc + buf * BUFSZ;
#pragma unroll
        for (int j = 0; j < 4; j++) {
            float4 v = aReg[j];
            uint2 hi2, lo2;
            __nv_bfloat16 hx = __float2bfloat16_rn(v.x), hy = __float2bfloat16_rn(v.y);
            __nv_bfloat16 hz = __float2bfloat16_rn(v.z), hw = __float2bfloat16_rn(v.w);
            { __nv_bfloat162 t0 = __halves2bfloat162(hx, hy); memcpy(&hi2.x, &t0, 4);
              __nv_bfloat162 t1 = __halves2bfloat162(hz, hw); memcpy(&hi2.y, &t1, 4); }
            lo2.x = pkbf2(v.x - __bfloat162float(hx), v.y - __bfloat162float(hy));
            lo2.y = pkbf2(v.z - __bfloat162float(hz), v.w - __bfloat162float(hw));
            uint32_t off = arow * APB + (ahalf * 16 + 4 * j) * 2;
            *(uint2*)(A + off)            = hi2;
            *(uint2*)(A + TM * APB + off) = lo2;
        }
        char* Bp = smc + buf * BUFSZ + ABUF;
#pragma unroll
        for (int p = 0; p < 6; p++) {
            int u   = p * 256 + tid;
            int mat = (u >= 768);
            int v   = mat ? (u - 768) : u;     // FIXED: was u & 767
            int n   = v >> 2, q = v & 3;
            *(uint4*)(Bp + (mat ? FO * APB : 0) + n * APB + q * 16) = bReg[p];
        }
    };

    auto domma = [&](int buf) {
        const char* A = smc + buf * BUFSZ;
        const char* B = A + ABUF;
#pragma unroll
        for (int ks = 0; ks < 2; ks++) {
            const int cb = (ks * 16 + (lane & 3) * 2) * 2;   // k byte offset
            uint32_t ah[2][4], al[2][4];
#pragma unroll
            for (int mt = 0; mt < 2; mt++) {
                const char* base = A + (warp_m * 32 + mt * 16 + (lane >> 2)) * APB + cb;
                ah[mt][0] = *(const uint32_t*)(base);
                ah[mt][1] = *(const uint32_t*)(base + 8 * APB);
                ah[mt][2] = *(const uint32_t*)(base + 16);
                ah[mt][3] = *(const uint32_t*)(base + 8 * APB + 16);
                const char* bl = base + TM * APB;
                al[mt][0] = *(const uint32_t*)(bl);
                al[mt][1] = *(const uint32_t*)(bl + 8 * APB);
                al[mt][2] = *(const uint32_t*)(bl + 16);
                al[mt][3] = *(const uint32_t*)(bl + 8 * APB + 16);
            }
#pragma unroll
            for (int nt = 0; nt < 12; nt++) {
                const char* bb = B + (warp_n * 96 + nt * 8 + (lane >> 2)) * APB + cb;
                uint32_t bh0 = *(const uint32_t*)(bb);
                uint32_t bh1 = *(const uint32_t*)(bb + 16);
                uint32_t bl0 = *(const uint32_t*)(bb + FO * APB);
                uint32_t bl1 = *(const uint32_t*)(bb + FO * APB + 16);
#pragma unroll
                for (int mt = 0; mt < 2; mt++) {
                    mma16816(acc[mt][nt], ah[mt], bh0, bh1);
                    mma16816(acc[mt][nt], al[mt], bh0, bh1);
                    mma16816(acc[mt][nt], ah[mt], bl0, bl1);
                }
            }
        }
    };

    loadA(0); loadB(0);
    stsAll(0);
    __syncthreads();

    for (int ch = 0; ch < NCH; ch++) {
        const int buf = ch & 1;
        if (ch + 1 < NCH) { loadA((ch + 1) * KC); loadB((ch + 1) * KC); }
        domma(buf);
        if (ch + 1 < NCH) stsAll(buf ^ 1);
        __syncthreads();
    }

    // ---- dump accumulators to epilogue smem [TM][EPIP] ----
    float* epi = (float*)smc;
#pragma unroll
    for (int mt = 0; mt < 2; mt++)
#pragma unroll
        for (int nt = 0; nt < 12; nt++) {
            int r = warp_m * 32 + mt * 16 + (lane >> 2);
            int c = warp_n * 96 + nt * 8 + (lane & 3) * 2;
            float2 v0 = make_float2(acc[mt][nt][0], acc[mt][nt][1]);
            float2 v1 = make_float2(acc[mt][nt][2], acc[mt][nt][3]);
            *(float2*)(epi + (size_t)r * EPIP + c)       = v0;
            *(float2*)(epi + (size_t)(r + 8) * EPIP + c) = v1;
        }
    __syncthreads();

    // ---- per-token epilogue (one thread per token) ----
    if (tid < TM) {
        float* r = epi + (size_t)tid * EPIP;

        const float av = alpha[0];
        const float a  = 1.0f / (1.0f + __expf(-av));
        int num = nump ? *nump : 8;
        if (num < 1)  num = 1;
        if (num > Ff) num = Ff;

        for (int f = 0; f < Ff; ++f) {
            r[f]          += b_top[f];
            r[Ff + f]     += b_feat[f];
            float g = r[2 * Ff + f] + b_gates[f];
            r[2 * Ff + f] = 1.0f / (1.0f + __expf(-g));
        }

        // dense branch: softmax(feat) . gates
        float m2 = -3.4e38f;
        for (int f = 0; f < Ff; ++f) m2 = fmaxf(m2, r[Ff + f]);
        float s2 = 0.0f, ds = 0.0f;
        for (int f = 0; f < Ff; ++f) {
            float e = __expf(r[Ff + f] - m2);
            s2 += e;
            ds += e * r[2 * Ff + f];
        }
        float dense = ds / s2;

        // top-k branch: streaming selection + softmax over selected
        float v0 = 0.0f, se = 0.0f, ta = 0.0f;
        for (int t = 0; t < num; ++t) {
            float best = -3.4e38f; int bi = 0;
            for (int f = 0; f < Ff; ++f) {
                float v = r[f];
                if (v > best) { best = v; bi = f; }
            }
            if (t == 0) v0 = best;
            float e = __expf(best - v0);
            se += e;
            ta += e * r[2 * Ff + bi];
            r[bi] = -3.4e38f;
        }
        float topp = ta / se;

        out[tok0 + tid] = a * topp + (1.0f - a) * dense;
    }
}

extern "C" void kernel_launch(void* const* d_in, const int* in_sizes, int n_in,
                              void* d_out, int out_size) {
    const float* x   = (const float*)d_in[0];
    const float* Wt  = (const float*)d_in[1];
    const float* bt  = (const float*)d_in[2];
    const float* Wf  = (const float*)d_in[3];
    const float* bfi = (const float*)d_in[4];
    const float* Wg  = (const float*)d_in[5];
    const float* bg  = (const float*)d_in[6];
    const float* al  = (const float*)d_in[7];
    const int*   nm  = (n_in > 8) ? (const int*)d_in[8] : nullptr;
    float* out = (float*)d_out;

    repack_kernel<<<(FO * Dd + 255) / 256, 256>>>(Wt, Wf, Wg);

    cudaFuncSetAttribute(moe_mma_kernel,
                         cudaFuncAttributeMaxDynamicSharedMemorySize, SMEMSZ);
    moe_mma_kernel<<<TOKENS / TM, 256, SMEMSZ>>>(x, bt, bfi, bg, al, nm, out);
}

// round 5
// speedup vs baseline: 2.4704x; 1.1016x over previous
#include <cuda_runtime.h>
#include <cuda_bf16.h>
#include <cstdint>

// Problem constants: B=8, S=2048, D=1024, F=64, TOPK=8
#define Dd     1024
#define Ff     64
#define FO     192            // 3*F fused outputs (top | feat | gates)
#define TM     128            // tokens per CTA
#define KC     64             // K chunk (elements)
#define NCH    (Dd / KC)      // 16
#define TOKENS 16384
#define PIT    144            // smem row pitch bytes (128B data + 16 pad)
#define ABUF   (2 * TM * PIT)     // 36864 B  (A hi + A lo)
#define BBUF   (2 * FO * PIT)     // 55296 B  (B hi + B lo)
#define BUFSZ  (ABUF + BBUF)      // 92160 B
#define SMEMSZ (2 * BUFSZ)        // 184320 B (double buffered; epi overlays)
#define EPIP   194                // epilogue row pitch (floats)

// Repacked weights, bf16 hi/lo split, n-major [FO][Dd]
__device__ __nv_bfloat16 g_Whi[FO * Dd];
__device__ __nv_bfloat16 g_Wlo[FO * Dd];

__device__ __forceinline__ void mma16816(float* c, const uint32_t* a,
                                         uint32_t b0, uint32_t b1) {
    asm("mma.sync.aligned.m16n8k16.row.col.f32.bf16.bf16.f32 "
        "{%0,%1,%2,%3}, {%4,%5,%6,%7}, {%8,%9}, {%0,%1,%2,%3};"
        : "+f"(c[0]), "+f"(c[1]), "+f"(c[2]), "+f"(c[3])
        : "r"(a[0]), "r"(a[1]), "r"(a[2]), "r"(a[3]), "r"(b0), "r"(b1));
}
#define LDSM4(R, addr)                                                        \
    asm volatile("ldmatrix.sync.aligned.m8n8.x4.shared.b16 {%0,%1,%2,%3}, [%4];" \
                 : "=r"((R)[0]), "=r"((R)[1]), "=r"((R)[2]), "=r"((R)[3])     \
                 : "r"(addr))

__device__ __forceinline__ uint32_t s2u(const void* p) {
    uint32_t a;
    asm("{ .reg .u64 t; cvta.to.shared.u64 t, %1; cvt.u32.u64 %0, t; }"
        : "=r"(a) : "l"(p));
    return a;
}
__device__ __forceinline__ uint32_t pkbf2(float a, float b) {
    __nv_bfloat162 t = __halves2bfloat162(__float2bfloat16_rn(a),
                                          __float2bfloat16_rn(b));
    uint32_t u; memcpy(&u, &t, 4); return u;
}

// Coalesced repack: blocks 0..127 transpose W_top/W_feat tiles; blocks 128..383 copy W_gates.
__global__ __launch_bounds__(256)
void repack_kernel(const float* __restrict__ Wt,
                   const float* __restrict__ Wf,
                   const float* __restrict__ Wg) {
    int b = blockIdx.x;
    if (b < 128) {
        __shared__ float tile[32][33];
        int ntile = b & 3, ktile = b >> 2;
        int tx = threadIdx.x & 31, ty = threadIdx.x >> 5;  // 32 x 8
        int n0 = ntile * 32, k0 = ktile * 32;
        const float* src = (n0 < Ff) ? Wt : Wf;
        int nb = (n0 < Ff) ? n0 : (n0 - Ff);
#pragma unroll
        for (int r = 0; r < 32; r += 8)
            tile[ty + r][tx] = src[(size_t)(k0 + ty + r) * Ff + nb + tx];
        __syncthreads();
#pragma unroll
        for (int r = 0; r < 32; r += 8) {
            float w = tile[tx][ty + r];
            __nv_bfloat16 hi = __float2bfloat16_rn(w);
            float lo = w - __bfloat162float(hi);
            size_t o = (size_t)(n0 + ty + r) * Dd + k0 + tx;
            g_Whi[o] = hi;
            g_Wlo[o] = __float2bfloat16_rn(lo);
        }
    } else {
        int i = (b - 128) * 256 + threadIdx.x;   // Ff*Dd = 65536 elems
        if (i < Ff * Dd) {
            float w = Wg[i];                      // already n-major
            __nv_bfloat16 hi = __float2bfloat16_rn(w);
            float lo = w - __bfloat162float(hi);
            size_t o = (size_t)(2 * Ff) * Dd + i;
            g_Whi[o] = hi;
            g_Wlo[o] = __float2bfloat16_rn(lo);
        }
    }
}

__global__ __launch_bounds__(256, 1)
void moe_mma_kernel(const float* __restrict__ x,
                    const float* __restrict__ b_top,
                    const float* __restrict__ b_feat,
                    const float* __restrict__ b_gates,
                    const float* __restrict__ alpha,
                    const int*   __restrict__ nump,
                    float* __restrict__ out) {
    extern __shared__ char smc[];

    const int tid    = threadIdx.x;
    const int wid    = tid >> 5;
    const int lane   = tid & 31;
    const int warp_m = wid & 3;     // M 32-row block
    const int warp_n = wid >> 2;    // N 96-col block
    const int tok0   = blockIdx.x * TM;
    const uint32_t smemBase = s2u(smc);

    float acc[2][12][4];
#pragma unroll
    for (int i = 0; i < 2; i++)
#pragma unroll
        for (int j = 0; j < 12; j++)
#pragma unroll
            for (int q = 0; q < 4; q++) acc[i][j][q] = 0.0f;

    // ---- A: gmem fp32 -> regs -> (convert) smem bf16 hi/lo ----
    const int arow  = tid >> 1;      // token row 0..127
    const int ahalf = tid & 1;       // k half (32 floats)
    float4 aReg[8];

    auto loadA = [&](int kb) {
        const float* gx = x + (size_t)(tok0 + arow) * Dd + kb + ahalf * 32;
#pragma unroll
        for (int j = 0; j < 8; j++) aReg[j] = *(const float4*)(gx + 4 * j);
    };
    auto stsA = [&](int buf) {
        char* A = smc + buf * BUFSZ;
#pragma unroll
        for (int j = 0; j < 8; j++) {
            float4 v = aReg[j];
            uint2 hi2, lo2;
            __nv_bfloat16 hx = __float2bfloat16_rn(v.x), hy = __float2bfloat16_rn(v.y);
            __nv_bfloat16 hz = __float2bfloat16_rn(v.z), hw = __float2bfloat16_rn(v.w);
            { __nv_bfloat162 t0 = __halves2bfloat162(hx, hy); memcpy(&hi2.x, &t0, 4);
              __nv_bfloat162 t1 = __halves2bfloat162(hz, hw); memcpy(&hi2.y, &t1, 4); }
            lo2.x = pkbf2(v.x - __bfloat162float(hx), v.y - __bfloat162float(hy));
            lo2.y = pkbf2(v.z - __bfloat162float(hz), v.w - __bfloat162float(hw));
            uint32_t off = arow * PIT + (ahalf * 32 + 4 * j) * 2;
            *(uint2*)(A + off)            = hi2;
            *(uint2*)(A + TM * PIT + off) = lo2;
        }
    };

    // ---- B: gmem bf16 -> smem via cp.async (no regs, no convert) ----
    auto cpB = [&](int kb, int buf) {
        uint32_t bdst = smemBase + buf * BUFSZ + ABUF;
#pragma unroll
        for (int p = 0; p < 12; p++) {
            int u   = p * 256 + tid;          // 0..3071
            int mat = (u >= 1536);
            int v   = mat ? (u - 1536) : u;   // 192 rows x 8 16B-segs
            int n   = v >> 3, q = v & 7;
            const __nv_bfloat16* src =
                (mat ? g_Wlo : g_Whi) + (size_t)n * Dd + kb + q * 8;
            uint32_t dst = bdst + (mat ? FO * PIT : 0) + n * PIT + q * 16;
            asm volatile("cp.async.cg.shared.global [%0], [%1], 16;"
                         :: "r"(dst), "l"(src));
        }
    };

    // ---- ldmatrix lane address bases ----
    const uint32_t aLaneOff =
        ((lane & 7) + ((lane >> 3) & 1) * 8) * PIT + (lane >> 4) * 16;
    const uint32_t bLaneOff =
        ((lane & 7) + (lane >> 4) * 8) * PIT + ((lane >> 3) & 1) * 16;
    const uint32_t aBase0 = smemBase + warp_m * 32 * PIT + aLaneOff;
    const uint32_t bBase0 = smemBase + ABUF + warp_n * 96 * PIT + bLaneOff;

    auto domma = [&](int buf) {
        uint32_t A0 = aBase0 + buf * BUFSZ;
        uint32_t B0 = bBase0 + buf * BUFSZ;
#pragma unroll
        for (int ks = 0; ks < 4; ks++) {
            const uint32_t kb = ks * 32;
            uint32_t ah0[4], ah1[4], al0[4], al1[4];
            LDSM4(ah0, A0 + kb);
            LDSM4(ah1, A0 + 16 * PIT + kb);
            LDSM4(al0, A0 + TM * PIT + kb);
            LDSM4(al1, A0 + TM * PIT + 16 * PIT + kb);
#pragma unroll
            for (int ntp = 0; ntp < 6; ntp++) {
                uint32_t bh[4], bl[4];
                LDSM4(bh, B0 + ntp * 16 * PIT + kb);
                LDSM4(bl, B0 + FO * PIT + ntp * 16 * PIT + kb);
                // nt = 2*ntp (bh[0],bh[1]) and 2*ntp+1 (bh[2],bh[3])
                mma16816(acc[0][2 * ntp],     ah0, bh[0], bh[1]);
                mma16816(acc[1][2 * ntp],     ah1, bh[0], bh[1]);
                mma16816(acc[0][2 * ntp],     al0, bh[0], bh[1]);
                mma16816(acc[1][2 * ntp],     al1, bh[0], bh[1]);
                mma16816(acc[0][2 * ntp],     ah0, bl[0], bl[1]);
                mma16816(acc[1][2 * ntp],     ah1, bl[0], bl[1]);
                mma16816(acc[0][2 * ntp + 1], ah0, bh[2], bh[3]);
                mma16816(acc[1][2 * ntp + 1], ah1, bh[2], bh[3]);
                mma16816(acc[0][2 * ntp + 1], al0, bh[2], bh[3]);
                mma16816(acc[1][2 * ntp + 1], al1, bh[2], bh[3]);
                mma16816(acc[0][2 * ntp + 1], ah0, bl[2], bl[3]);
                mma16816(acc[1][2 * ntp + 1], ah1, bl[2], bl[3]);
            }
        }
    };

    // ---- prologue ----
    cpB(0, 0);
    asm volatile("cp.async.commit_group;");
    loadA(0);
    stsA(0);
    asm volatile("cp.async.wait_group 0;" ::: "memory");
    __syncthreads();

    // ---- mainloop ----
    for (int ch = 0; ch < NCH; ch++) {
        const int buf = ch & 1;
        if (ch + 1 < NCH) {
            cpB((ch + 1) * KC, buf ^ 1);
            asm volatile("cp.async.commit_group;");
            loadA((ch + 1) * KC);
        }
        domma(buf);
        if (ch + 1 < NCH) {
            stsA(buf ^ 1);
            asm volatile("cp.async.wait_group 0;" ::: "memory");
        }
        __syncthreads();
    }

    // ---- dump accumulators to epilogue smem [TM][EPIP] ----
    float* epi = (float*)smc;
#pragma unroll
    for (int mt = 0; mt < 2; mt++)
#pragma unroll
        for (int nt = 0; nt < 12; nt++) {
            int r = warp_m * 32 + mt * 16 + (lane >> 2);
            int c = warp_n * 96 + nt * 8 + (lane & 3) * 2;
            float2 v0 = make_float2(acc[mt][nt][0], acc[mt][nt][1]);
            float2 v1 = make_float2(acc[mt][nt][2], acc[mt][nt][3]);
            *(float2*)(epi + (size_t)r * EPIP + c)       = v0;
            *(float2*)(epi + (size_t)(r + 8) * EPIP + c) = v1;
        }
    __syncthreads();

    // ---- per-token epilogue (one thread per token) ----
    if (tid < TM) {
        float* r = epi + (size_t)tid * EPIP;

        const float av = alpha[0];
        const float a  = 1.0f / (1.0f + __expf(-av));
        int num = nump ? *nump : 8;
        if (num < 1)  num = 1;
        if (num > Ff) num = Ff;

        for (int f = 0; f < Ff; ++f) {
            r[f]          += b_top[f];
            r[Ff + f]     += b_feat[f];
            float g = r[2 * Ff + f] + b_gates[f];
            r[2 * Ff + f] = 1.0f / (1.0f + __expf(-g));
        }

        // dense branch: softmax(feat) . gates
        float m2 = -3.4e38f;
        for (int f = 0; f < Ff; ++f) m2 = fmaxf(m2, r[Ff + f]);
        float s2 = 0.0f, ds = 0.0f;
        for (int f = 0; f < Ff; ++f) {
            float e = __expf(r[Ff + f] - m2);
            s2 += e;
            ds += e * r[2 * Ff + f];
        }
        float dense = ds / s2;

        // top-k branch: streaming selection + softmax over selected
        float v0 = 0.0f, se = 0.0f, ta = 0.0f;
        for (int t = 0; t < num; ++t) {
            float best = -3.4e38f; int bi = 0;
            for (int f = 0; f < Ff; ++f) {
                float v = r[f];
                if (v > best) { best = v; bi = f; }
            }
            if (t == 0) v0 = best;
            float e = __expf(best - v0);
            se += e;
            ta += e * r[2 * Ff + bi];
            r[bi] = -3.4e38f;
        }
        float topp = ta / se;

        out[tok0 + tid] = a * topp + (1.0f - a) * dense;
    }
}

extern "C" void kernel_launch(void* const* d_in, const int* in_sizes, int n_in,
                              void* d_out, int out_size) {
    const float* x   = (const float*)d_in[0];
    const float* Wt  = (const float*)d_in[1];
    const float* bt  = (const float*)d_in[2];
    const float* Wf  = (const float*)d_in[3];
    const float* bfi = (const float*)d_in[4];
    const float* Wg  = (const float*)d_in[5];
    const float* bg  = (const float*)d_in[6];
    const float* al  = (const float*)d_in[7];
    const int*   nm  = (n_in > 8) ? (const int*)d_in[8] : nullptr;
    float* out = (float*)d_out;

    repack_kernel<<<384, 256>>>(Wt, Wf, Wg);

    cudaFuncSetAttribute(moe_mma_kernel,
                         cudaFuncAttributeMaxDynamicSharedMemorySize, SMEMSZ);
    moe_mma_kernel<<<TOKENS / TM, 256, SMEMSZ>>>(x, bt, bfi, bg, al, nm, out);
}

// round 6
// speedup vs baseline: 2.5421x; 1.0290x over previous
#include <cuda_runtime.h>
#include <cuda_bf16.h>
#include <cstdint>

// Problem constants: B=8, S=2048, D=1024, F=64, TOPK=8
#define Dd     1024
#define Ff     64
#define FO     192            // 3*F fused outputs (top | feat | gates)
#define TMX    112            // max tokens per CTA (7 m16 tiles)
#define KC     64             // K chunk (elements)
#define NCH    (Dd / KC)      // 16
#define TOKENS 16384
#define NCTA   148            // 136 CTAs x 112 tokens + 12 CTAs x 96 tokens
#define PIT    144            // smem row pitch bytes (128B data + 16 pad)
#define ALOOF  (TMX * PIT)        // A lo offset inside A region
#define ABUF   (2 * TMX * PIT)    // 32256 B (A hi + A lo)
#define BBUF   (2 * FO * PIT)     // 55296 B (B hi + B lo)
#define BUFSZ  (ABUF + BBUF)      // 87552 B
#define SMEMSZ (2 * BUFSZ)        // 175104 B (double buffered; epi overlays)
#define EPIP   194                // epilogue row pitch (floats)

// Repacked weights, bf16 hi/lo split, n-major [FO][Dd]
__device__ __nv_bfloat16 g_Whi[FO * Dd];
__device__ __nv_bfloat16 g_Wlo[FO * Dd];

__device__ __forceinline__ void mma16816(float* c, const uint32_t* a,
                                         uint32_t b0, uint32_t b1) {
    asm("mma.sync.aligned.m16n8k16.row.col.f32.bf16.bf16.f32 "
        "{%0,%1,%2,%3}, {%4,%5,%6,%7}, {%8,%9}, {%0,%1,%2,%3};"
        : "+f"(c[0]), "+f"(c[1]), "+f"(c[2]), "+f"(c[3])
        : "r"(a[0]), "r"(a[1]), "r"(a[2]), "r"(a[3]), "r"(b0), "r"(b1));
}
#define LDSM4(R, addr)                                                        \
    asm volatile("ldmatrix.sync.aligned.m8n8.x4.shared.b16 {%0,%1,%2,%3}, [%4];" \
                 : "=r"((R)[0]), "=r"((R)[1]), "=r"((R)[2]), "=r"((R)[3])     \
                 : "r"(addr))
#define LDSM2(R, addr)                                                        \
    asm volatile("ldmatrix.sync.aligned.m8n8.x2.shared.b16 {%0,%1}, [%2];"    \
                 : "=r"((R)[0]), "=r"((R)[1])                                 \
                 : "r"(addr))

__device__ __forceinline__ uint32_t s2u(const void* p) {
    uint32_t a;
    asm("{ .reg .u64 t; cvta.to.shared.u64 t, %1; cvt.u32.u64 %0, t; }"
        : "=r"(a) : "l"(p));
    return a;
}
__device__ __forceinline__ uint32_t pkbf2(float a, float b) {
    __nv_bfloat162 t = __halves2bfloat162(__float2bfloat16_rn(a),
                                          __float2bfloat16_rn(b));
    uint32_t u; memcpy(&u, &t, 4); return u;
}

// Coalesced repack: blocks 0..127 transpose W_top/W_feat tiles; blocks 128..383 copy W_gates.
__global__ __launch_bounds__(256)
void repack_kernel(const float* __restrict__ Wt,
                   const float* __restrict__ Wf,
                   const float* __restrict__ Wg) {
    int b = blockIdx.x;
    if (b < 128) {
        __shared__ float tile[32][33];
        int ntile = b & 3, ktile = b >> 2;
        int tx = threadIdx.x & 31, ty = threadIdx.x >> 5;  // 32 x 8
        int n0 = ntile * 32, k0 = ktile * 32;
        const float* src = (n0 < Ff) ? Wt : Wf;
        int nb = (n0 < Ff) ? n0 : (n0 - Ff);
#pragma unroll
        for (int r = 0; r < 32; r += 8)
            tile[ty + r][tx] = src[(size_t)(k0 + ty + r) * Ff + nb + tx];
        __syncthreads();
#pragma unroll
        for (int r = 0; r < 32; r += 8) {
            float w = tile[tx][ty + r];
            __nv_bfloat16 hi = __float2bfloat16_rn(w);
            float lo = w - __bfloat162float(hi);
            size_t o = (size_t)(n0 + ty + r) * Dd + k0 + tx;
            g_Whi[o] = hi;
            g_Wlo[o] = __float2bfloat16_rn(lo);
        }
    } else {
        int i = (b - 128) * 256 + threadIdx.x;   // Ff*Dd = 65536 elems
        if (i < Ff * Dd) {
            float w = Wg[i];                      // already n-major
            __nv_bfloat16 hi = __float2bfloat16_rn(w);
            float lo = w - __bfloat162float(hi);
            size_t o = (size_t)(2 * Ff) * Dd + i;
            g_Whi[o] = hi;
            g_Wlo[o] = __float2bfloat16_rn(lo);
        }
    }
}

__global__ __launch_bounds__(256, 1)
void moe_mma_kernel(const float* __restrict__ x,
                    const float* __restrict__ b_top,
                    const float* __restrict__ b_feat,
                    const float* __restrict__ b_gates,
                    const float* __restrict__ alpha,
                    const int*   __restrict__ nump,
                    float* __restrict__ out) {
    extern __shared__ char smc[];

    const int tid  = threadIdx.x;
    const int wid  = tid >> 5;
    const int lane = tid & 31;
    const int cid  = blockIdx.x;
    const uint32_t smemBase = s2u(smc);

    // Work distribution: 136 CTAs x 7 m16-tiles, 12 CTAs x 6 m16-tiles
    const int  T    = (cid < 136) ? 7 : 6;
    const int  tok0 = (cid < 136) ? cid * 112 : 136 * 112 + (cid - 136) * 96;
    const int  Mloc = T * 16;
    const bool t7   = (T == 7);

    // Warp owns N-slice of 24 cols (3 n8-tiles), ALL m-tiles
    float acc[7][3][4];
#pragma unroll
    for (int mt = 0; mt < 7; mt++)
#pragma unroll
        for (int j = 0; j < 3; j++)
#pragma unroll
            for (int q = 0; q < 4; q++) acc[mt][j][q] = 0.0f;

    // ---- A: gmem fp32 -> regs -> (convert) smem bf16 hi/lo ----
    const int arow  = tid >> 1;      // 0..127 (rows >= Mloc skipped)
    const int ahalf = tid & 1;       // k half (32 floats)
    const bool aAct = (arow < Mloc);
    float4 aReg[8];

    auto loadA = [&](int kb) {
        if (!aAct) return;
        const float* gx = x + (size_t)(tok0 + arow) * Dd + kb + ahalf * 32;
#pragma unroll
        for (int j = 0; j < 8; j++) aReg[j] = *(const float4*)(gx + 4 * j);
    };
    auto stsA = [&](int buf) {
        if (!aAct) return;
        char* A = smc + buf * BUFSZ;
#pragma unroll
        for (int j = 0; j < 8; j++) {
            float4 v = aReg[j];
            uint2 hi2, lo2;
            __nv_bfloat16 hx = __float2bfloat16_rn(v.x), hy = __float2bfloat16_rn(v.y);
            __nv_bfloat16 hz = __float2bfloat16_rn(v.z), hw = __float2bfloat16_rn(v.w);
            { __nv_bfloat162 t0 = __halves2bfloat162(hx, hy); memcpy(&hi2.x, &t0, 4);
              __nv_bfloat162 t1 = __halves2bfloat162(hz, hw); memcpy(&hi2.y, &t1, 4); }
            lo2.x = pkbf2(v.x - __bfloat162float(hx), v.y - __bfloat162float(hy));
            lo2.y = pkbf2(v.z - __bfloat162float(hz), v.w - __bfloat162float(hw));
            uint32_t off = arow * PIT + (ahalf * 32 + 4 * j) * 2;
            *(uint2*)(A + off)         = hi2;
            *(uint2*)(A + ALOOF + off) = lo2;
        }
    };

    // ---- B: gmem bf16 -> smem via cp.async ----
    auto cpB = [&](int kb, int buf) {
        uint32_t bdst = smemBase + buf * BUFSZ + ABUF;
#pragma unroll
        for (int p = 0; p < 12; p++) {
            int u   = p * 256 + tid;          // 0..3071
            int mat = (u >= 1536);
            int v   = mat ? (u - 1536) : u;   // 192 rows x 8 16B-segs
            int n   = v >> 3, q = v & 7;
            const __nv_bfloat16* src =
                (mat ? g_Wlo : g_Whi) + (size_t)n * Dd + kb + q * 8;
            uint32_t dst = bdst + (mat ? FO * PIT : 0) + n * PIT + q * 16;
            asm volatile("cp.async.cg.shared.global [%0], [%1], 16;"
                         :: "r"(dst), "l"(src));
        }
    };

    // ---- ldmatrix lane address bases ----
    const uint32_t aLaneOff =
        ((lane & 7) + ((lane >> 3) & 1) * 8) * PIT + (lane >> 4) * 16;
    const int l2 = lane & 15;
    const uint32_t bLaneOff = (l2 & 7) * PIT + (l2 >> 3) * 16;
    const uint32_t aBase0 = smemBase + aLaneOff;
    const uint32_t bBase0 = smemBase + ABUF + (wid * 24) * PIT + bLaneOff;

    auto domma = [&](int buf) {
        uint32_t A0 = aBase0 + buf * BUFSZ;
        uint32_t B0 = bBase0 + buf * BUFSZ;
#pragma unroll
        for (int ks = 0; ks < 4; ks++) {
            const uint32_t kb = ks * 32;
            uint32_t bh[3][2], bl[3][2];
#pragma unroll
            for (int j = 0; j < 3; j++) {
                LDSM2(bh[j], B0 + j * 8 * PIT + kb);
                LDSM2(bl[j], B0 + FO * PIT + j * 8 * PIT + kb);
            }
            uint32_t ah[7][4], al[7][4];
#pragma unroll
            for (int mt = 0; mt < 7; mt++)
                if (mt < 6 || t7) {
                    LDSM4(ah[mt], A0 + mt * 16 * PIT + kb);
                    LDSM4(al[mt], A0 + ALOOF + mt * 16 * PIT + kb);
                }
            // term 1: Ah * Bh  (all independent)
#pragma unroll
            for (int mt = 0; mt < 7; mt++)
                if (mt < 6 || t7)
#pragma unroll
                    for (int j = 0; j < 3; j++)
                        mma16816(acc[mt][j], ah[mt], bh[j][0], bh[j][1]);
            // term 2: Al * Bh
#pragma unroll
            for (int mt = 0; mt < 7; mt++)
                if (mt < 6 || t7)
#pragma unroll
                    for (int j = 0; j < 3; j++)
                        mma16816(acc[mt][j], al[mt], bh[j][0], bh[j][1]);
            // term 3: Ah * Bl
#pragma unroll
            for (int mt = 0; mt < 7; mt++)
                if (mt < 6 || t7)
#pragma unroll
                    for (int j = 0; j < 3; j++)
                        mma16816(acc[mt][j], ah[mt], bl[j][0], bl[j][1]);
        }
    };

    // ---- prologue ----
    cpB(0, 0);
    asm volatile("cp.async.commit_group;");
    loadA(0);
    stsA(0);
    asm volatile("cp.async.wait_group 0;" ::: "memory");
    __syncthreads();

    // ---- mainloop ----
    for (int ch = 0; ch < NCH; ch++) {
        const int buf = ch & 1;
        if (ch + 1 < NCH) {
            cpB((ch + 1) * KC, buf ^ 1);
            asm volatile("cp.async.commit_group;");
            loadA((ch + 1) * KC);
        }
        domma(buf);
        if (ch + 1 < NCH) {
            stsA(buf ^ 1);
            asm volatile("cp.async.wait_group 0;" ::: "memory");
        }
        __syncthreads();
    }

    // ---- dump accumulators to epilogue smem [TMX][EPIP] ----
    float* epi = (float*)smc;
#pragma unroll
    for (int mt = 0; mt < 7; mt++)
        if (mt < 6 || t7)
#pragma unroll
            for (int j = 0; j < 3; j++) {
                int r = mt * 16 + (lane >> 2);
                int c = wid * 24 + j * 8 + (lane & 3) * 2;
                *(float2*)(epi + (size_t)r * EPIP + c) =
                    make_float2(acc[mt][j][0], acc[mt][j][1]);
                *(float2*)(epi + (size_t)(r + 8) * EPIP + c) =
                    make_float2(acc[mt][j][2], acc[mt][j][3]);
            }
    __syncthreads();

    // ---- per-token epilogue (one thread per token) ----
    if (tid < Mloc) {
        float* r = epi + (size_t)tid * EPIP;

        const float av = alpha[0];
        const float a  = 1.0f / (1.0f + __expf(-av));
        int num = nump ? *nump : 8;
        if (num < 1)  num = 1;
        if (num > Ff) num = Ff;

        for (int f = 0; f < Ff; ++f) {
            r[f]          += b_top[f];
            r[Ff + f]     += b_feat[f];
            float g = r[2 * Ff + f] + b_gates[f];
            r[2 * Ff + f] = 1.0f / (1.0f + __expf(-g));
        }

        // dense branch: softmax(feat) . gates
        float m2 = -3.4e38f;
        for (int f = 0; f < Ff; ++f) m2 = fmaxf(m2, r[Ff + f]);
        float s2 = 0.0f, ds = 0.0f;
        for (int f = 0; f < Ff; ++f) {
            float e = __expf(r[Ff + f] - m2);
            s2 += e;
            ds += e * r[2 * Ff + f];
        }
        float dense = ds / s2;

        // top-k branch: streaming selection + softmax over selected
        float v0 = 0.0f, se = 0.0f, ta = 0.0f;
        for (int t = 0; t < num; ++t) {
            float best = -3.4e38f; int bi = 0;
            for (int f = 0; f < Ff; ++f) {
                float v = r[f];
                if (v > best) { best = v; bi = f; }
            }
            if (t == 0) v0 = best;
            float e = __expf(best - v0);
            se += e;
            ta += e * r[2 * Ff + bi];
            r[bi] = -3.4e38f;
        }
        float topp = ta / se;

        out[tok0 + tid] = a * topp + (1.0f - a) * dense;
    }
}

extern "C" void kernel_launch(void* const* d_in, const int* in_sizes, int n_in,
                              void* d_out, int out_size) {
    const float* x   = (const float*)d_in[0];
    const float* Wt  = (const float*)d_in[1];
    const float* bt  = (const float*)d_in[2];
    const float* Wf  = (const float*)d_in[3];
    const float* bfi = (const float*)d_in[4];
    const float* Wg  = (const float*)d_in[5];
    const float* bg  = (const float*)d_in[6];
    const float* al  = (const float*)d_in[7];
    const int*   nm  = (n_in > 8) ? (const int*)d_in[8] : nullptr;
    float* out = (float*)d_out;

    repack_kernel<<<384, 256>>>(Wt, Wf, Wg);

    cudaFuncSetAttribute(moe_mma_kernel,
                         cudaFuncAttributeMaxDynamicSharedMemorySize, SMEMSZ);
    moe_mma_kernel<<<NCTA, 256, SMEMSZ>>>(x, bt, bfi, bg, al, nm, out);
}

// round 7
// speedup vs baseline: 2.7584x; 1.0851x over previous
#include <cuda_runtime.h>
#include <cuda_bf16.h>
#include <cstdint>

// Problem constants: B=8, S=2048, D=1024, F=64, TOPK=8
#define Dd     1024
#define Ff     64
#define FO     192            // 3*F fused outputs (top | feat | gates)
#define TMX    112            // max tokens per CTA (7 m16 tiles)
#define KC     64             // K chunk (elements)
#define NCH    (Dd / KC)      // 16
#define TOKENS 16384
#define NCTA   148            // 136 CTAs x 112 tokens + 12 CTAs x 96 tokens
#define PIT32  288            // A fp32 smem row pitch bytes (256 + 32)
#define PIT    144            // B bf16 smem row pitch bytes (128 + 16)
#define ABUF32 (TMX * PIT32)      // 32256 B (A fp32)
#define BBUF   (2 * FO * PIT)     // 55296 B (B hi + B lo)
#define BUFSZ  (ABUF32 + BBUF)    // 87552 B
#define SMEMSZ (2 * BUFSZ)        // 175104 B (double buffered; epi overlays)
#define EPIP   194                // epilogue row pitch (floats)

// Repacked weights, bf16 hi/lo split, n-major [FO][Dd]
__device__ __nv_bfloat16 g_Whi[FO * Dd];
__device__ __nv_bfloat16 g_Wlo[FO * Dd];

__device__ __forceinline__ void mma16816(float* c, const uint32_t* a,
                                         uint32_t b0, uint32_t b1) {
    asm("mma.sync.aligned.m16n8k16.row.col.f32.bf16.bf16.f32 "
        "{%0,%1,%2,%3}, {%4,%5,%6,%7}, {%8,%9}, {%0,%1,%2,%3};"
        : "+f"(c[0]), "+f"(c[1]), "+f"(c[2]), "+f"(c[3])
        : "r"(a[0]), "r"(a[1]), "r"(a[2]), "r"(a[3]), "r"(b0), "r"(b1));
}
#define LDSM4(R, addr)                                                        \
    asm volatile("ldmatrix.sync.aligned.m8n8.x4.shared.b16 {%0,%1,%2,%3}, [%4];" \
                 : "=r"((R)[0]), "=r"((R)[1]), "=r"((R)[2]), "=r"((R)[3])     \
                 : "r"(addr))

__device__ __forceinline__ uint32_t s2u(const void* p) {
    uint32_t a;
    asm("{ .reg .u64 t; cvta.to.shared.u64 t, %1; cvt.u32.u64 %0, t; }"
        : "=r"(a) : "l"(p));
    return a;
}
// Split a pair of fp32 into bf16x2 hi and bf16x2 lo (residual).
__device__ __forceinline__ void split2(float2 f, uint32_t& hi, uint32_t& lo) {
    __nv_bfloat162 h2 = __float22bfloat162_rn(f);        // low = f.x, high = f.y
    uint32_t h; memcpy(&h, &h2, 4);
    float h0 = __uint_as_float(h << 16);
    float h1 = __uint_as_float(h & 0xFFFF0000u);
    __nv_bfloat162 l2 = __float22bfloat162_rn(make_float2(f.x - h0, f.y - h1));
    memcpy(&lo, &l2, 4);
    hi = h;
}

// Coalesced repack: blocks 0..127 transpose W_top/W_feat tiles; blocks 128..383 copy W_gates.
__global__ __launch_bounds__(256)
void repack_kernel(const float* __restrict__ Wt,
                   const float* __restrict__ Wf,
                   const float* __restrict__ Wg) {
    int b = blockIdx.x;
    if (b < 128) {
        __shared__ float tile[32][33];
        int ntile = b & 3, ktile = b >> 2;
        int tx = threadIdx.x & 31, ty = threadIdx.x >> 5;  // 32 x 8
        int n0 = ntile * 32, k0 = ktile * 32;
        const float* src = (n0 < Ff) ? Wt : Wf;
        int nb = (n0 < Ff) ? n0 : (n0 - Ff);
#pragma unroll
        for (int r = 0; r < 32; r += 8)
            tile[ty + r][tx] = src[(size_t)(k0 + ty + r) * Ff + nb + tx];
        __syncthreads();
#pragma unroll
        for (int r = 0; r < 32; r += 8) {
            float w = tile[tx][ty + r];
            __nv_bfloat16 hi = __float2bfloat16_rn(w);
            float lo = w - __bfloat162float(hi);
            size_t o = (size_t)(n0 + ty + r) * Dd + k0 + tx;
            g_Whi[o] = hi;
            g_Wlo[o] = __float2bfloat16_rn(lo);
        }
    } else {
        int i = (b - 128) * 256 + threadIdx.x;   // Ff*Dd = 65536 elems
        if (i < Ff * Dd) {
            float w = Wg[i];                      // already n-major
            __nv_bfloat16 hi = __float2bfloat16_rn(w);
            float lo = w - __bfloat162float(hi);
            size_t o = (size_t)(2 * Ff) * Dd + i;
            g_Whi[o] = hi;
            g_Wlo[o] = __float2bfloat16_rn(lo);
        }
    }
}

__global__ __launch_bounds__(256, 1)
void moe_mma_kernel(const float* __restrict__ x,
                    const float* __restrict__ b_top,
                    const float* __restrict__ b_feat,
                    const float* __restrict__ b_gates,
                    const float* __restrict__ alpha,
                    const int*   __restrict__ nump,
                    float* __restrict__ out) {
    extern __shared__ char smc[];

    const int tid  = threadIdx.x;
    const int wid  = tid >> 5;
    const int lane = tid & 31;
    const int cid  = blockIdx.x;
    const uint32_t smemBase = s2u(smc);

    // Work distribution: 136 CTAs x 7 m16-tiles, 12 CTAs x 6 m16-tiles
    const int  T    = (cid < 136) ? 7 : 6;
    const int  tok0 = (cid < 136) ? cid * 112 : 136 * 112 + (cid - 136) * 96;
    const int  Mloc = T * 16;
    const bool t7   = (T == 7);

    // Warp owns N-slice of 24 cols (3 n8-tiles), ALL m-tiles
    float acc[7][3][4];
#pragma unroll
    for (int mt = 0; mt < 7; mt++)
#pragma unroll
        for (int j = 0; j < 3; j++)
#pragma unroll
            for (int q = 0; q < 4; q++) acc[mt][j][q] = 0.0f;

    // ---- A: gmem fp32 -> smem fp32 via cp.async (7 x 16B segs/thread) ----
    auto cpA = [&](int kb, int buf) {
        uint32_t adst = smemBase + buf * BUFSZ;
#pragma unroll
        for (int p = 0; p < 7; p++) {
            int s   = p * 256 + tid;      // 0..1791
            int row = s >> 4, seg = s & 15;
            if (row < Mloc) {
                const float* src = x + (size_t)(tok0 + row) * Dd + kb + seg * 4;
                uint32_t dst = adst + row * PIT32 + seg * 16;
                asm volatile("cp.async.cg.shared.global [%0], [%1], 16;"
                             :: "r"(dst), "l"(src));
            }
        }
    };
    // ---- B: gmem bf16 -> smem via cp.async ----
    auto cpB = [&](int kb, int buf) {
        uint32_t bdst = smemBase + buf * BUFSZ + ABUF32;
#pragma unroll
        for (int p = 0; p < 12; p++) {
            int u   = p * 256 + tid;          // 0..3071
            int mat = (u >= 1536);
            int v   = mat ? (u - 1536) : u;   // 192 rows x 8 16B-segs
            int n   = v >> 3, q = v & 7;
            const __nv_bfloat16* src =
                (mat ? g_Wlo : g_Whi) + (size_t)n * Dd + kb + q * 8;
            uint32_t dst = bdst + (mat ? FO * PIT : 0) + n * PIT + q * 16;
            asm volatile("cp.async.cg.shared.global [%0], [%1], 16;"
                         :: "r"(dst), "l"(src));
        }
    };

    // ---- lane address bases ----
    // B ldmatrix.x4: lanes 0-15 -> hi tiles (k0-7, k8-15), lanes 16-31 -> lo tiles
    const int ll = lane & 15;
    const uint32_t bLaneOff = (ll & 7) * PIT + ((ll >> 3) & 1) * 16
                            + (lane >> 4) * (FO * PIT);
    const uint32_t bBase0 = smemBase + ABUF32 + (wid * 24) * PIT + bLaneOff;
    // A scalar LDS.64: row = lane>>2, col pair = (lane&3)*2
    const uint32_t aLaneOff = (lane >> 2) * PIT32 + (lane & 3) * 8;

    auto domma = [&](int buf) {
        const char* A0 = smc + buf * BUFSZ + aLaneOff;
        uint32_t    B0 = bBase0 + buf * BUFSZ;
#pragma unroll
        for (int ks = 0; ks < 4; ks++) {
            // B fragments: one LDSM4 per n8-tile gives bh (R0,R1) + bl (R2,R3)
            uint32_t bf[3][4];
#pragma unroll
            for (int j = 0; j < 3; j++)
                LDSM4(bf[j], B0 + j * 8 * PIT + ks * 32);
            // A fragments: scalar LDS.64 + inline hi/lo split
            const char* Ak = A0 + ks * 64;
            uint32_t ah[7][4], al[7][4];
#pragma unroll
            for (int mt = 0; mt < 7; mt++)
                if (mt < 6 || t7) {
                    const char* base = Ak + mt * 16 * PIT32;
                    float2 p0 = *(const float2*)(base);
                    float2 p1 = *(const float2*)(base + 8 * PIT32);
                    float2 p2 = *(const float2*)(base + 32);
                    float2 p3 = *(const float2*)(base + 8 * PIT32 + 32);
                    split2(p0, ah[mt][0], al[mt][0]);
                    split2(p1, ah[mt][1], al[mt][1]);
                    split2(p2, ah[mt][2], al[mt][2]);
                    split2(p3, ah[mt][3], al[mt][3]);
                }
            // term 1: Ah * Bh
#pragma unroll
            for (int mt = 0; mt < 7; mt++)
                if (mt < 6 || t7)
#pragma unroll
                    for (int j = 0; j < 3; j++)
                        mma16816(acc[mt][j], ah[mt], bf[j][0], bf[j][1]);
            // term 2: Al * Bh
#pragma unroll
            for (int mt = 0; mt < 7; mt++)
                if (mt < 6 || t7)
#pragma unroll
                    for (int j = 0; j < 3; j++)
                        mma16816(acc[mt][j], al[mt], bf[j][0], bf[j][1]);
            // term 3: Ah * Bl
#pragma unroll
            for (int mt = 0; mt < 7; mt++)
                if (mt < 6 || t7)
#pragma unroll
                    for (int j = 0; j < 3; j++)
                        mma16816(acc[mt][j], ah[mt], bf[j][2], bf[j][3]);
        }
    };

    // ---- prologue ----
    cpA(0, 0); cpB(0, 0);
    asm volatile("cp.async.commit_group;");

    // ---- mainloop: 2-buffer cp.async pipeline ----
    for (int ch = 0; ch < NCH; ch++) {
        const int buf = ch & 1;
        if (ch + 1 < NCH) {
            cpA((ch + 1) * KC, buf ^ 1);
            cpB((ch + 1) * KC, buf ^ 1);
            asm volatile("cp.async.commit_group;");
            asm volatile("cp.async.wait_group 1;" ::: "memory");
        } else {
            asm volatile("cp.async.wait_group 0;" ::: "memory");
        }
        __syncthreads();      // chunk ch resident for all warps
        domma(buf);
        __syncthreads();      // all warps done reading buf before next cp overwrites it
    }

    // ---- dump accumulators to epilogue smem [TMX][EPIP] ----
    float* epi = (float*)smc;
#pragma unroll
    for (int mt = 0; mt < 7; mt++)
        if (mt < 6 || t7)
#pragma unroll
            for (int j = 0; j < 3; j++) {
                int r = mt * 16 + (lane >> 2);
                int c = wid * 24 + j * 8 + (lane & 3) * 2;
                *(float2*)(epi + (size_t)r * EPIP + c) =
                    make_float2(acc[mt][j][0], acc[mt][j][1]);
                *(float2*)(epi + (size_t)(r + 8) * EPIP + c) =
                    make_float2(acc[mt][j][2], acc[mt][j][3]);
            }
    __syncthreads();

    // ---- per-token epilogue (one thread per token) ----
    if (tid < Mloc) {
        float* r = epi + (size_t)tid * EPIP;

        const float av = alpha[0];
        const float a  = 1.0f / (1.0f + __expf(-av));
        int num = nump ? *nump : 8;
        if (num < 1)  num = 1;
        if (num > Ff) num = Ff;

        for (int f = 0; f < Ff; ++f) {
            r[f]          += b_top[f];
            r[Ff + f]     += b_feat[f];
            float g = r[2 * Ff + f] + b_gates[f];
            r[2 * Ff + f] = 1.0f / (1.0f + __expf(-g));
        }

        // dense branch: softmax(feat) . gates
        float m2 = -3.4e38f;
        for (int f = 0; f < Ff; ++f) m2 = fmaxf(m2, r[Ff + f]);
        float s2 = 0.0f, ds = 0.0f;
        for (int f = 0; f < Ff; ++f) {
            float e = __expf(r[Ff + f] - m2);
            s2 += e;
            ds += e * r[2 * Ff + f];
        }
        float dense = ds / s2;

        // top-k branch: streaming selection + softmax over selected
        float v0 = 0.0f, se = 0.0f, ta = 0.0f;
        for (int t = 0; t < num; ++t) {
            float best = -3.4e38f; int bi = 0;
            for (int f = 0; f < Ff; ++f) {
                float v = r[f];
                if (v > best) { best = v; bi = f; }
            }
            if (t == 0) v0 = best;
            float e = __expf(best - v0);
            se += e;
            ta += e * r[2 * Ff + bi];
            r[bi] = -3.4e38f;
        }
        float topp = ta / se;

        out[tok0 + tid] = a * topp + (1.0f - a) * dense;
    }
}

extern "C" void kernel_launch(void* const* d_in, const int* in_sizes, int n_in,
                              void* d_out, int out_size) {
    const float* x   = (const float*)d_in[0];
    const float* Wt  = (const float*)d_in[1];
    const float* bt  = (const float*)d_in[2];
    const float* Wf  = (const float*)d_in[3];
    const float* bfi = (const float*)d_in[4];
    const float* Wg  = (const float*)d_in[5];
    const float* bg  = (const float*)d_in[6];
    const float* al  = (const float*)d_in[7];
    const int*   nm  = (n_in > 8) ? (const int*)d_in[8] : nullptr;
    float* out = (float*)d_out;

    repack_kernel<<<384, 256>>>(Wt, Wf, Wg);

    cudaFuncSetAttribute(moe_mma_kernel,
                         cudaFuncAttributeMaxDynamicSharedMemorySize, SMEMSZ);
    moe_mma_kernel<<<NCTA, 256, SMEMSZ>>>(x, bt, bfi, bg, al, nm, out);
}